// round 4
// baseline (speedup 1.0000x reference)
#include <cuda_runtime.h>
#include <cuda_fp16.h>
#include <math.h>
#include <stdint.h>

// ---------------- problem constants ----------------
#define Bsz     2
#define Hdim    256
#define Wdim    256
#define Cc      192
#define NHEADS  6
#define HID     768
#define TOK     (Bsz*Hdim*Wdim)      // 131072 tokens
#define NWIN    2048

// ---------------- scratch ----------------
__device__ __half g_xn16[(size_t)TOK*Cc];     // LN outputs (fp16)
__device__ float  g_q32 [(size_t)TOK*Cc];     // q (fp32)
__device__ float  g_kv32[(size_t)TOK*(Cc/2)]; // kv (fp32)
__device__ __half g_aw16[(size_t)TOK*Cc];     // attention out (fp16)
__device__ float  g_x2  [(size_t)TOK*Cc];     // trunk after attn residual (fp32)
__device__ __half g_h116[(size_t)TOK*HID];    // h1 (fp16)
__device__ __half g_h16 [(size_t)TOK*HID];    // h  (fp16)
// fp16 transposed weights [N][K]
__device__ __half g_wq16   [192*192];
__device__ __half g_wkv16  [96*192];
__device__ __half g_wproj16[192*192];
__device__ __half g_w1f16  [768*192];
__device__ __half g_w2f16  [192*768];

__device__ __forceinline__ float gelu_exact(float x) {
    return 0.5f * x * (1.0f + erff(x * 0.70710678118654752f));
}

__device__ __forceinline__ void cp_async16(uint32_t dst, const void* src, int srcsize) {
    asm volatile("cp.async.cg.shared.global [%0], [%1], 16, %2;"
                 :: "r"(dst), "l"(src), "r"(srcsize));
}
__device__ __forceinline__ void cp_commit() {
    asm volatile("cp.async.commit_group;");
}
template<int N_>
__device__ __forceinline__ void cp_wait() {
    asm volatile("cp.async.wait_group %0;" :: "n"(N_));
}

// ---------------- weight transpose + fp16 convert: out[n][k] = in[k][n] ----------------
__global__ __launch_bounds__(256)
void wtrans_kernel(const float* __restrict__ in, __half* __restrict__ out, int K, int N) {
    __shared__ float t[32][33];
    int kb = blockIdx.y*32, nb = blockIdx.x*32;
    int tx = threadIdx.x & 31, ty = threadIdx.x >> 5;   // 32x8
    for (int i = ty; i < 32; i += 8)
        if (kb+i < K && nb+tx < N) t[i][tx] = in[(size_t)(kb+i)*N + nb+tx];
    __syncthreads();
    for (int i = ty; i < 32; i += 8)
        if (nb+i < N && kb+tx < K)
            out[(size_t)(nb+i)*K + kb+tx] = __float2half(t[tx][i]);
}

// ---------------- LayerNorm (fp32 in, fp16 out) ----------------
__global__ __launch_bounds__(256)
void ln_kernel(const float* __restrict__ x, const float* __restrict__ g,
               const float* __restrict__ b, __half* __restrict__ out) {
    int warp = (blockIdx.x * blockDim.x + threadIdx.x) >> 5;
    int lane = threadIdx.x & 31;
    if (warp >= TOK) return;
    const float* xr = x + (size_t)warp * Cc;
    float v[6];
    float s = 0.f, s2 = 0.f;
#pragma unroll
    for (int j = 0; j < 6; j++) {
        v[j] = xr[lane + 32*j];
        s += v[j]; s2 += v[j]*v[j];
    }
#pragma unroll
    for (int o = 16; o; o >>= 1) {
        s  += __shfl_xor_sync(0xffffffffu, s,  o);
        s2 += __shfl_xor_sync(0xffffffffu, s2, o);
    }
    float mu  = s  * (1.f/Cc);
    float var = s2 * (1.f/Cc) - mu*mu;
    float r   = rsqrtf(var + 1e-5f);
    __half* orow = out + (size_t)warp * Cc;
#pragma unroll
    for (int j = 0; j < 6; j++) {
        int c = lane + 32*j;
        orow[c] = __float2half((v[j]-mu)*r*g[c] + b[c]);
    }
}

// ---------------- fp16 tensor-core GEMM, 4-stage cp.async pipeline ----------------
// C[M,N] = A[M,K](fp16) @ Wt[N,K](fp16)^T  (+bias)(+gelu)(+res), fp32 accumulate.
// Tile 128x128x16, 256 threads (8 warps 2x4), warp tile 64x32, m16n8k16.
// EPI: 1=bias, 2=bias+gelu, 3=bias+residual
#define BM 128
#define BN 128
#define BK 16
#define STG 4
#define LDSTR 24   // smem row stride in halves (bank-conflict-free)

template<int EPI, typename OutT>
__global__ __launch_bounds__(256)
void mma_gemm(const __half* __restrict__ A, const __half* __restrict__ Wt,
              const float* __restrict__ bias, const float* __restrict__ res,
              OutT* __restrict__ C, int M, int N, int K) {
    __shared__ __half As[STG][BM][LDSTR];
    __shared__ __half Bs[STG][BN][LDSTR];

    const int tid  = threadIdx.x;
    const int lane = tid & 31;
    const int warp = tid >> 5;
    const int wm = (warp >> 2) * 64;
    const int wn = (warp & 3) * 32;
    const int m0 = blockIdx.y * BM;
    const int n0 = blockIdx.x * BN;
    const int gr = lane >> 2;
    const int gc = lane & 3;

    uint32_t as_base = (uint32_t)__cvta_generic_to_shared(&As[0][0][0]);
    uint32_t bs_base = (uint32_t)__cvta_generic_to_shared(&Bs[0][0][0]);

    float acc[4][4][4];
#pragma unroll
    for (int i = 0; i < 4; i++)
#pragma unroll
        for (int j = 0; j < 4; j++)
#pragma unroll
            for (int t = 0; t < 4; t++) acc[i][j][t] = 0.f;

    const int niter = K / BK;

    // one cp16 for A + one for B per thread per stage
    const int arow = tid >> 1;
    const int acol = (tid & 1) * 8;      // halves
    auto load_stage = [&](int s, int k0) {
        {
            uint32_t dst = as_base + (uint32_t)(((s*BM + arow)*LDSTR + acol) * 2);
            const __half* src = A + (size_t)(m0 + arow)*K + k0 + acol;
            cp_async16(dst, src, 16);
        }
        {
            int col = n0 + arow;
            uint32_t dst = bs_base + (uint32_t)(((s*BN + arow)*LDSTR + acol) * 2);
            const __half* src = Wt + (size_t)(col < N ? col : 0)*K + k0 + acol;
            cp_async16(dst, src, col < N ? 16 : 0);
        }
    };

#pragma unroll
    for (int s = 0; s < 3; s++) {
        if (s < niter) load_stage(s, s*BK);
        cp_commit();
    }

    for (int it = 0; it < niter; it++) {
        cp_wait<2>();
        __syncthreads();
        if (it + 3 < niter) load_stage((it + 3) & 3, (it + 3) * BK);
        cp_commit();

        const int s = it & 3;
        unsigned af[4][4];
#pragma unroll
        for (int mt = 0; mt < 4; mt++) {
            int mr = wm + mt*16 + gr;
            af[mt][0] = *(const unsigned*)&As[s][mr    ][2*gc    ];
            af[mt][1] = *(const unsigned*)&As[s][mr + 8][2*gc    ];
            af[mt][2] = *(const unsigned*)&As[s][mr    ][2*gc + 8];
            af[mt][3] = *(const unsigned*)&As[s][mr + 8][2*gc + 8];
        }
        unsigned bf[4][2];
#pragma unroll
        for (int nt = 0; nt < 4; nt++) {
            int nc = wn + nt*8 + gr;
            bf[nt][0] = *(const unsigned*)&Bs[s][nc][2*gc    ];
            bf[nt][1] = *(const unsigned*)&Bs[s][nc][2*gc + 8];
        }
#pragma unroll
        for (int mt = 0; mt < 4; mt++)
#pragma unroll
            for (int nt = 0; nt < 4; nt++) {
                asm volatile(
                    "mma.sync.aligned.m16n8k16.row.col.f32.f16.f16.f32 "
                    "{%0,%1,%2,%3}, {%4,%5,%6,%7}, {%8,%9}, {%0,%1,%2,%3};"
                    : "+f"(acc[mt][nt][0]), "+f"(acc[mt][nt][1]),
                      "+f"(acc[mt][nt][2]), "+f"(acc[mt][nt][3])
                    : "r"(af[mt][0]), "r"(af[mt][1]), "r"(af[mt][2]), "r"(af[mt][3]),
                      "r"(bf[nt][0]), "r"(bf[nt][1]));
            }
        __syncthreads();
    }

    // ---- epilogue ----
#pragma unroll
    for (int mt = 0; mt < 4; mt++) {
#pragma unroll
        for (int nt = 0; nt < 4; nt++) {
            int col = n0 + wn + nt*8 + gc*2;
            if (col < N) {
#pragma unroll
                for (int hh = 0; hh < 2; hh++) {
                    int row = m0 + wm + mt*16 + gr + hh*8;
                    float v0 = acc[mt][nt][hh*2+0];
                    float v1 = acc[mt][nt][hh*2+1];
                    if (EPI >= 1) { v0 += bias[col]; v1 += bias[col+1]; }
                    if (EPI == 2) { v0 = gelu_exact(v0); v1 = gelu_exact(v1); }
                    if (EPI == 3) {
                        const float* rr = res + (size_t)row*N + col;
                        v0 += rr[0]; v1 += rr[1];
                    }
                    if (sizeof(OutT) == 2) {
                        *(__half2*)((__half*)C + (size_t)row*N + col) = __floats2half2_rn(v0, v1);
                    } else {
                        *(float2*)((float*)C + (size_t)row*N + col) = make_float2(v0, v1);
                    }
                }
            }
        }
    }
}

// ---------------- fused windowed attention (fp32 q/kv in, fp16 out) ----------------
__global__ __launch_bounds__(384)
void attn_kernel(const float* __restrict__ qbuf, const float* __restrict__ kvbuf,
                 const float* __restrict__ bias_table, __half* __restrict__ aw) {
    __shared__ float sk[NHEADS*16*32];
    __shared__ float sv[NHEADS*16*32];
    const int wid = blockIdx.x;
    const int b  = wid >> 10;
    const int wy = (wid >> 5) & 31;
    const int wx = wid & 31;
    const int base = b*65536 + wy*8*256 + wx*8;
    const int tid = threadIdx.x;

    for (int ii = tid; ii < 2*16*192; ii += 384) {
        int sel = ii / (16*192);
        int rem = ii - sel*(16*192);
        int tok = rem / 192;
        int hd  = rem - tok*192;
        int i   = hd / 96;
        int j   = (hd / 48) & 1;
        int c48 = hd % 48;
        int p1 = tok >> 2, p2 = tok & 3;
        int grow = base + (p1*2 + i)*256 + (p2*2 + j);
        float val = kvbuf[(size_t)grow*96 + sel*48 + c48];
        float* dst = sel ? sv : sk;
        dst[(hd >> 5)*512 + tok*32 + (hd & 31)] = val;
    }
    __syncthreads();

    const int h  = tid / 64;
    const int qt = tid % 64;
    const int qr = qt >> 3, qc = qt & 7;
    const int qrow = base + qr*256 + qc;

    float q[32];
    const float* qp = qbuf + (size_t)qrow*Cc + h*32;
#pragma unroll
    for (int d4 = 0; d4 < 8; d4++) {
        float4 t = *(const float4*)(qp + d4*4);
        q[d4*4+0]=t.x; q[d4*4+1]=t.y; q[d4*4+2]=t.z; q[d4*4+3]=t.w;
    }

    const float SCALE = 0.17677669529663687f;
    const int qr2 = qr >> 1, qc2 = qc >> 1;
    float sc[16];
    float m = -1e30f;
#pragma unroll
    for (int kv = 0; kv < 16; kv++) {
        const float* kp = sk + h*512 + kv*32;
        float dot = 0.f;
#pragma unroll
        for (int d = 0; d < 32; d++) dot += q[d]*kp[d];
        int kr = kv >> 2, kc = kv & 3;
        int rel = (qr2 - kr + 3)*7 + (qc2 - kc + 3);
        float s = dot*SCALE + bias_table[rel*NHEADS + h];
        sc[kv] = s;
        m = fmaxf(m, s);
    }
    float sum = 0.f;
#pragma unroll
    for (int kv = 0; kv < 16; kv++) { sc[kv] = expf(sc[kv]-m); sum += sc[kv]; }
    float inv = 1.f/sum;
    float o[32];
#pragma unroll
    for (int d = 0; d < 32; d++) o[d] = 0.f;
#pragma unroll
    for (int kv = 0; kv < 16; kv++) {
        float p = sc[kv]*inv;
        const float* vp = sv + h*512 + kv*32;
#pragma unroll
        for (int d = 0; d < 32; d++) o[d] += p*vp[d];
    }
    __half* op = aw + (size_t)qrow*Cc + h*32;
#pragma unroll
    for (int d2 = 0; d2 < 16; d2++) {
        *(__half2*)(op + d2*2) = __floats2half2_rn(o[d2*2], o[d2*2+1]);
    }
}

// ---------------- depthwise 5x5 conv branch (fp16 in/out, fp32 compute) ----------------
__global__ __launch_bounds__(256)
void dwconv_kernel(const __half* __restrict__ h1, const float* __restrict__ dwk,
                   const float* __restrict__ dwb, __half* __restrict__ out) {
    __shared__ float2 s[144][32];
    const int cb = blockIdx.z % 12;
    const int b  = blockIdx.z / 12;
    const int y0 = blockIdx.y * 8, x0 = blockIdx.x * 8;
    const int tid = threadIdx.x;

    for (int ii = tid; ii < 144*32; ii += 256) {
        int pix = ii >> 5, c2 = ii & 31;
        int py = pix / 12, px = pix % 12;
        int gy = y0 + py - 2, gx = x0 + px - 2;
        float2 v = make_float2(0.f, 0.f);
        if (gy >= 0 && gy < Hdim && gx >= 0 && gx < Wdim) {
            size_t row = (size_t)(b*65536 + gy*256 + gx);
            __half2 hv = *(const __half2*)(h1 + row*HID + cb*64 + c2*2);
            v = __half22float2(hv);
        }
        s[pix][c2] = v;
    }
    __syncthreads();

    const int c2 = tid & 31;
    const int pq = tid >> 5;
    const int c0 = cb*64 + c2*2;

    float2 wk[25];
#pragma unroll
    for (int t = 0; t < 25; t++) {
        wk[t].x = dwk[(size_t)c0*25 + t];
        wk[t].y = dwk[(size_t)(c0+1)*25 + t];
    }
    float2 bb = make_float2(dwb[c0], dwb[c0+1]);

    float2 win[5][5];
#pragma unroll
    for (int dx = 0; dx < 5; dx++)
#pragma unroll
        for (int dy = 0; dy < 5; dy++)
            win[dx][dy] = s[(pq+dy)*12 + dx][c2];

#pragma unroll
    for (int px = 0; px < 8; px++) {
        float2 acc = make_float2(0.f, 0.f);
#pragma unroll
        for (int dy = 0; dy < 5; dy++)
#pragma unroll
            for (int dx = 0; dx < 5; dx++) {
                float2 v = win[dx][dy];
                float2 w = wk[dy*5+dx];
                acc.x += v.x*w.x;
                acc.y += v.y*w.y;
            }
        float2 center = win[2][2];
        float rx = center.x + gelu_exact(acc.x + bb.x);
        float ry = center.y + gelu_exact(acc.y + bb.y);
        size_t row = (size_t)(b*65536 + (y0+pq)*256 + (x0+px));
        *(__half2*)(out + row*HID + c0) = __floats2half2_rn(rx, ry);
        if (px < 7) {
#pragma unroll
            for (int dx = 0; dx < 4; dx++)
#pragma unroll
                for (int dy = 0; dy < 5; dy++)
                    win[dx][dy] = win[dx+1][dy];
#pragma unroll
            for (int dy = 0; dy < 5; dy++)
                win[4][dy] = s[(pq+dy)*12 + (px+5)][c2];
        }
    }
}

// ---------------- launch ----------------
extern "C" void kernel_launch(void* const* d_in, const int* in_sizes, int n_in,
                              void* d_out, int out_size) {
    const float* x          = (const float*)d_in[0];
    const float* g1         = (const float*)d_in[1];
    const float* be1        = (const float*)d_in[2];
    const float* wq         = (const float*)d_in[3];
    const float* bq         = (const float*)d_in[4];
    const float* wkv        = (const float*)d_in[5];
    const float* bkv        = (const float*)d_in[6];
    const float* bias_table = (const float*)d_in[7];
    const float* wproj      = (const float*)d_in[8];
    const float* bproj      = (const float*)d_in[9];
    const float* g2         = (const float*)d_in[10];
    const float* be2        = (const float*)d_in[11];
    const float* w1f        = (const float*)d_in[12];
    const float* b1f        = (const float*)d_in[13];
    const float* dwk        = (const float*)d_in[14];
    const float* dwb        = (const float*)d_in[15];
    const float* w2f        = (const float*)d_in[16];
    const float* b2f        = (const float*)d_in[17];
    float* out = (float*)d_out;

    __half *xn16, *aw16, *h116, *h16;
    __half *wq16, *wkv16, *wproj16, *w1f16, *w2f16;
    float *q32, *kv32, *x2;
    cudaGetSymbolAddress((void**)&xn16,    g_xn16);
    cudaGetSymbolAddress((void**)&aw16,    g_aw16);
    cudaGetSymbolAddress((void**)&h116,    g_h116);
    cudaGetSymbolAddress((void**)&h16,     g_h16);
    cudaGetSymbolAddress((void**)&q32,     g_q32);
    cudaGetSymbolAddress((void**)&kv32,    g_kv32);
    cudaGetSymbolAddress((void**)&x2,      g_x2);
    cudaGetSymbolAddress((void**)&wq16,    g_wq16);
    cudaGetSymbolAddress((void**)&wkv16,   g_wkv16);
    cudaGetSymbolAddress((void**)&wproj16, g_wproj16);
    cudaGetSymbolAddress((void**)&w1f16,   g_w1f16);
    cudaGetSymbolAddress((void**)&w2f16,   g_w2f16);

    // 0. weight transpose + fp16 convert
    wtrans_kernel<<<dim3(6, 6),  256>>>(wq,    wq16,    192, 192);
    wtrans_kernel<<<dim3(3, 6),  256>>>(wkv,   wkv16,   192, 96);
    wtrans_kernel<<<dim3(6, 6),  256>>>(wproj, wproj16, 192, 192);
    wtrans_kernel<<<dim3(24, 6), 256>>>(w1f,   w1f16,   192, 768);
    wtrans_kernel<<<dim3(6, 24), 256>>>(w2f,   w2f16,   768, 192);

    // 1. LN1 -> fp16
    ln_kernel<<<TOK/8, 256>>>(x, g1, be1, xn16);
    // 2. q = xn @ wq + bq (fp32 out)
    mma_gemm<1, float><<<dim3(2, TOK/BM), 256>>>(xn16, wq16, bq, nullptr, q32, TOK, 192, 192);
    // 3. kv = xn @ wkv + bkv (fp32 out)
    mma_gemm<1, float><<<dim3(1, TOK/BM), 256>>>(xn16, wkv16, bkv, nullptr, kv32, TOK, 96, 192);
    // 4. attention -> fp16
    attn_kernel<<<NWIN, 384>>>(q32, kv32, bias_table, aw16);
    // 5. x2 = x + aw @ wproj + bproj (fp32)
    mma_gemm<3, float><<<dim3(2, TOK/BM), 256>>>(aw16, wproj16, bproj, x, x2, TOK, 192, 192);
    // 6. LN2 -> fp16
    ln_kernel<<<TOK/8, 256>>>(x2, g2, be2, xn16);
    // 7. h1 = gelu(xn2 @ w1f + b1f) -> fp16
    mma_gemm<2, __half><<<dim3(6, TOK/BM), 256>>>(xn16, w1f16, b1f, nullptr, h116, TOK, HID, 192);
    // 8. h = h1 + gelu(dwconv(h1)+dwb) -> fp16
    dwconv_kernel<<<dim3(32, 32, Bsz*12), 256>>>(h116, dwk, dwb, h16);
    // 9. out = x2 + h @ w2f + b2f (fp32)
    mma_gemm<3, float><<<dim3(2, TOK/BM), 256>>>(h16, w2f16, b2f, x2, out, TOK, 192, HID);
}

// round 6
// speedup vs baseline: 1.0218x; 1.0218x over previous
#include <cuda_runtime.h>
#include <math.h>
#include <stdint.h>

// ---------------- problem constants ----------------
#define Bsz     2
#define Hdim    256
#define Wdim    256
#define Cc      192
#define NHEADS  6
#define HID     768
#define TOK     (Bsz*Hdim*Wdim)      // 131072 tokens
#define NWIN    2048

// ---------------- scratch ----------------
__device__ float g_bufA[(size_t)TOK*Cc];    // xn / xn2
__device__ float g_bufB[(size_t)TOK*Cc];    // attention output (pre-proj)
__device__ float g_bufC[(size_t)TOK*Cc];    // x after attention residual
__device__ float g_bufD[(size_t)TOK*HID];   // q, later h1
__device__ float g_bufE[(size_t)TOK*HID];   // kv, later h
// fp32 transposed weights [N][K]
__device__ float g_wq32   [192*192];
__device__ float g_wkv32  [96*192];
__device__ float g_wproj32[192*192];
__device__ float g_w1f32  [768*192];
__device__ float g_w2f32  [192*768];

__device__ __forceinline__ float gelu_exact(float x) {
    return 0.5f * x * (1.0f + erff(x * 0.70710678118654752f));
}

__device__ __forceinline__ void cp_async16(uint32_t dst, const void* src) {
    asm volatile("cp.async.cg.shared.global [%0], [%1], 16;" :: "r"(dst), "l"(src));
}
__device__ __forceinline__ void cp_commit() {
    asm volatile("cp.async.commit_group;");
}
template<int N_>
__device__ __forceinline__ void cp_wait() {
    asm volatile("cp.async.wait_group %0;" :: "n"(N_));
}
__device__ __forceinline__ void ldsm_x4(unsigned& r0, unsigned& r1, unsigned& r2, unsigned& r3,
                                        uint32_t addr) {
    asm volatile("ldmatrix.sync.aligned.m8n8.x4.shared.b16 {%0,%1,%2,%3}, [%4];"
                 : "=r"(r0), "=r"(r1), "=r"(r2), "=r"(r3) : "r"(addr));
}

// ---------------- weight transpose fp32: out[n][k] = in[k][n] ----------------
__global__ __launch_bounds__(256)
void wtrans32_kernel(const float* __restrict__ in, float* __restrict__ out, int K, int N) {
    __shared__ float t[32][33];
    int kb = blockIdx.y*32, nb = blockIdx.x*32;
    int tx = threadIdx.x & 31, ty = threadIdx.x >> 5;
    for (int i = ty; i < 32; i += 8)
        if (kb+i < K && nb+tx < N) t[i][tx] = in[(size_t)(kb+i)*N + nb+tx];
    __syncthreads();
    for (int i = ty; i < 32; i += 8)
        if (nb+i < N && kb+tx < K)
            out[(size_t)(nb+i)*K + kb+tx] = t[tx][i];
}

// ---------------- LayerNorm ----------------
__global__ __launch_bounds__(256)
void ln_kernel(const float* __restrict__ x, const float* __restrict__ g,
               const float* __restrict__ b, float* __restrict__ out) {
    int warp = (blockIdx.x * blockDim.x + threadIdx.x) >> 5;
    int lane = threadIdx.x & 31;
    if (warp >= TOK) return;
    const float* xr = x + (size_t)warp * Cc;
    float v[6];
    float s = 0.f, s2 = 0.f;
#pragma unroll
    for (int j = 0; j < 6; j++) {
        v[j] = xr[lane + 32*j];
        s += v[j]; s2 += v[j]*v[j];
    }
#pragma unroll
    for (int o = 16; o; o >>= 1) {
        s  += __shfl_xor_sync(0xffffffffu, s,  o);
        s2 += __shfl_xor_sync(0xffffffffu, s2, o);
    }
    float mu  = s  * (1.f/Cc);
    float var = s2 * (1.f/Cc) - mu*mu;
    float r   = rsqrtf(var + 1e-5f);
    float* orow = out + (size_t)warp * Cc;
#pragma unroll
    for (int j = 0; j < 6; j++) {
        int c = lane + 32*j;
        orow[c] = (v[j]-mu)*r*g[c] + b[c];
    }
}

// ---------------- tf32 tensor-core GEMM: ldmatrix + 4-stage cp.async ----------------
// C[M,N] = A[M,K] @ Wt[N,K]^T  (+bias)(+gelu)(+res)
// Tile 128x128x16, 256 threads (8 warps 2x4), warp tile 64x32, m16n8k8 tf32.
// A smem [m][20] fp32, B smem [n][20] fp32 (stride 20 floats = 80B, 16B-aligned rows).
// EPI: 1=bias, 2=bias+gelu, 3=bias+residual
#define BM 128
#define BN 128
#define BK 16
#define STG 4
#define RSTR 20                       // floats per smem row
#define STGB (128*RSTR*4)             // bytes per stage (10240)

template<int EPI>
__global__ __launch_bounds__(256)
void mma_gemm(const float* __restrict__ A, const float* __restrict__ Wt,
              const float* __restrict__ bias, const float* __restrict__ res,
              float* __restrict__ C, int M, int N, int K) {
    extern __shared__ float smem[];
    const uint32_t sbase = (uint32_t)__cvta_generic_to_shared(smem);
    const uint32_t abase = sbase;                 // 4 stages A
    const uint32_t bbase = sbase + STG*STGB;      // 4 stages B

    const int tid  = threadIdx.x;
    const int lane = tid & 31;
    const int warp = tid >> 5;
    const int wm = (warp >> 2) * 64;
    const int wn = (warp & 3) * 32;
    const int m0 = blockIdx.y * BM;
    const int n0 = blockIdx.x * BN;
    const int gr = lane >> 2;
    const int gc = lane & 3;

    // ldmatrix per-thread source rows/cols
    const int a_r = wm + (lane & 15);              // + mt*16
    const int a_c = ((lane >> 4) & 1) * 4;         // + kb
    const int b_r = wn + (lane & 7) + ((lane & 16) ? 8 : 0);   // + pair*16
    const int b_c = ((lane >> 3) & 1) * 4;         // + kb

    float acc[4][4][4];
#pragma unroll
    for (int i = 0; i < 4; i++)
#pragma unroll
        for (int j = 0; j < 4; j++)
#pragma unroll
            for (int t = 0; t < 4; t++) acc[i][j][t] = 0.f;

    const int niter = K / BK;

    // staging: A 128x16 fp32 = 512 16B-chunks, B same; 2+2 per thread
    auto load_stage = [&](int s, int k0) {
#pragma unroll
        for (int h = 0; h < 2; h++) {
            int f = tid + h*256;
            int row = f >> 2, c4 = (f & 3) * 4;
            cp_async16(abase + (uint32_t)(s*STGB + (row*RSTR + c4)*4),
                       A + (size_t)(m0 + row)*K + k0 + c4);
        }
#pragma unroll
        for (int h = 0; h < 2; h++) {
            int f = tid + h*256;
            int row = f >> 2, c4 = (f & 3) * 4;
            int col = n0 + row;
            cp_async16(bbase + (uint32_t)(s*STGB + (row*RSTR + c4)*4),
                       Wt + (size_t)(col < N ? col : 0)*K + k0 + c4);
        }
        cp_commit();
    };

#pragma unroll
    for (int s = 0; s < 3; s++) {
        if (s < niter) load_stage(s, s*BK);
        else cp_commit();
    }

    for (int it = 0; it < niter; it++) {
        cp_wait<2>();
        __syncthreads();
        if (it + 3 < niter) load_stage((it + 3) & 3, (it + 3) * BK);
        else cp_commit();

        const int s = it & 3;
        const uint32_t a_st = abase + s*STGB;
        const uint32_t b_st = bbase + s*STGB;
#pragma unroll
        for (int ks = 0; ks < 2; ks++) {
            const int kb = ks * 8;
            unsigned af[4][4];
#pragma unroll
            for (int mt = 0; mt < 4; mt++) {
                uint32_t addr = a_st + (uint32_t)(((a_r + mt*16)*RSTR + kb + a_c) * 4);
                ldsm_x4(af[mt][0], af[mt][1], af[mt][2], af[mt][3], addr);
            }
            unsigned bf[4][2];
#pragma unroll
            for (int pr = 0; pr < 2; pr++) {
                uint32_t addr = b_st + (uint32_t)(((b_r + pr*16)*RSTR + kb + b_c) * 4);
                ldsm_x4(bf[pr*2][0], bf[pr*2][1], bf[pr*2+1][0], bf[pr*2+1][1], addr);
            }
#pragma unroll
            for (int mt = 0; mt < 4; mt++)
#pragma unroll
                for (int nt = 0; nt < 4; nt++) {
                    asm volatile(
                        "mma.sync.aligned.m16n8k8.row.col.f32.tf32.tf32.f32 "
                        "{%0,%1,%2,%3}, {%4,%5,%6,%7}, {%8,%9}, {%0,%1,%2,%3};"
                        : "+f"(acc[mt][nt][0]), "+f"(acc[mt][nt][1]),
                          "+f"(acc[mt][nt][2]), "+f"(acc[mt][nt][3])
                        : "r"(af[mt][0]), "r"(af[mt][1]), "r"(af[mt][2]), "r"(af[mt][3]),
                          "r"(bf[nt][0]), "r"(bf[nt][1]));
                }
        }
        __syncthreads();
    }

    // ---- epilogue ----
#pragma unroll
    for (int mt = 0; mt < 4; mt++) {
#pragma unroll
        for (int nt = 0; nt < 4; nt++) {
            int col = n0 + wn + nt*8 + gc*2;
            if (col < N) {
#pragma unroll
                for (int hh = 0; hh < 2; hh++) {
                    int row = m0 + wm + mt*16 + gr + hh*8;
                    float v0 = acc[mt][nt][hh*2+0];
                    float v1 = acc[mt][nt][hh*2+1];
                    if (EPI >= 1) { v0 += bias[col]; v1 += bias[col+1]; }
                    if (EPI == 2) { v0 = gelu_exact(v0); v1 = gelu_exact(v1); }
                    if (EPI == 3) {
                        const float* rr = res + (size_t)row*N + col;
                        v0 += rr[0]; v1 += rr[1];
                    }
                    *(float2*)(C + (size_t)row*N + col) = make_float2(v0, v1);
                }
            }
        }
    }
}

// ---------------- fused windowed attention ----------------
__global__ __launch_bounds__(384)
void attn_kernel(const float* __restrict__ qbuf, const float* __restrict__ kvbuf,
                 const float* __restrict__ bias_table, float* __restrict__ aw) {
    __shared__ float sk[NHEADS*16*32];
    __shared__ float sv[NHEADS*16*32];
    const int wid = blockIdx.x;
    const int b  = wid >> 10;
    const int wy = (wid >> 5) & 31;
    const int wx = wid & 31;
    const int base = b*65536 + wy*8*256 + wx*8;
    const int tid = threadIdx.x;

    for (int ii = tid; ii < 2*16*192; ii += 384) {
        int sel = ii / (16*192);
        int rem = ii - sel*(16*192);
        int tok = rem / 192;
        int hd  = rem - tok*192;
        int i   = hd / 96;
        int j   = (hd / 48) & 1;
        int c48 = hd % 48;
        int p1 = tok >> 2, p2 = tok & 3;
        int grow = base + (p1*2 + i)*256 + (p2*2 + j);
        float val = kvbuf[(size_t)grow*96 + sel*48 + c48];
        float* dst = sel ? sv : sk;
        dst[(hd >> 5)*512 + tok*32 + (hd & 31)] = val;
    }
    __syncthreads();

    const int h  = tid / 64;
    const int qt = tid % 64;
    const int qr = qt >> 3, qc = qt & 7;
    const int qrow = base + qr*256 + qc;

    float q[32];
    const float* qp = qbuf + (size_t)qrow*Cc + h*32;
#pragma unroll
    for (int d4 = 0; d4 < 8; d4++) {
        float4 t = *(const float4*)(qp + d4*4);
        q[d4*4+0]=t.x; q[d4*4+1]=t.y; q[d4*4+2]=t.z; q[d4*4+3]=t.w;
    }

    const float SCALE = 0.17677669529663687f;
    const int qr2 = qr >> 1, qc2 = qc >> 1;
    float sc[16];
    float m = -1e30f;
#pragma unroll
    for (int kv = 0; kv < 16; kv++) {
        const float* kp = sk + h*512 + kv*32;
        float dot = 0.f;
#pragma unroll
        for (int d = 0; d < 32; d++) dot += q[d]*kp[d];
        int kr = kv >> 2, kc = kv & 3;
        int rel = (qr2 - kr + 3)*7 + (qc2 - kc + 3);
        float s = dot*SCALE + bias_table[rel*NHEADS + h];
        sc[kv] = s;
        m = fmaxf(m, s);
    }
    float sum = 0.f;
#pragma unroll
    for (int kv = 0; kv < 16; kv++) { sc[kv] = expf(sc[kv]-m); sum += sc[kv]; }
    float inv = 1.f/sum;
    float o[32];
#pragma unroll
    for (int d = 0; d < 32; d++) o[d] = 0.f;
#pragma unroll
    for (int kv = 0; kv < 16; kv++) {
        float p = sc[kv]*inv;
        const float* vp = sv + h*512 + kv*32;
#pragma unroll
        for (int d = 0; d < 32; d++) o[d] += p*vp[d];
    }
    float* op = aw + (size_t)qrow*Cc + h*32;
#pragma unroll
    for (int d4 = 0; d4 < 8; d4++) {
        *(float4*)(op + d4*4) = make_float4(o[d4*4+0],o[d4*4+1],o[d4*4+2],o[d4*4+3]);
    }
}

// ---------------- depthwise 5x5 conv branch ----------------
__global__ __launch_bounds__(256)
void dwconv_kernel(const float* __restrict__ h1, const float* __restrict__ dwk,
                   const float* __restrict__ dwb, float* __restrict__ out) {
    __shared__ float2 s[144][32];
    const int cb = blockIdx.z % 12;
    const int b  = blockIdx.z / 12;
    const int y0 = blockIdx.y * 8, x0 = blockIdx.x * 8;
    const int tid = threadIdx.x;

    for (int ii = tid; ii < 144*32; ii += 256) {
        int pix = ii >> 5, c2 = ii & 31;
        int py = pix / 12, px = pix % 12;
        int gy = y0 + py - 2, gx = x0 + px - 2;
        float2 v = make_float2(0.f, 0.f);
        if (gy >= 0 && gy < Hdim && gx >= 0 && gx < Wdim) {
            size_t row = (size_t)(b*65536 + gy*256 + gx);
            v = *(const float2*)(h1 + row*HID + cb*64 + c2*2);
        }
        s[pix][c2] = v;
    }
    __syncthreads();

    const int c2 = tid & 31;
    const int pq = tid >> 5;
    const int c0 = cb*64 + c2*2;

    float2 wk[25];
#pragma unroll
    for (int t = 0; t < 25; t++) {
        wk[t].x = dwk[(size_t)c0*25 + t];
        wk[t].y = dwk[(size_t)(c0+1)*25 + t];
    }
    float2 bb = make_float2(dwb[c0], dwb[c0+1]);

    float2 win[5][5];
#pragma unroll
    for (int dx = 0; dx < 5; dx++)
#pragma unroll
        for (int dy = 0; dy < 5; dy++)
            win[dx][dy] = s[(pq+dy)*12 + dx][c2];

#pragma unroll
    for (int px = 0; px < 8; px++) {
        float2 acc = make_float2(0.f, 0.f);
#pragma unroll
        for (int dy = 0; dy < 5; dy++)
#pragma unroll
            for (int dx = 0; dx < 5; dx++) {
                float2 v = win[dx][dy];
                float2 w = wk[dy*5+dx];
                acc.x += v.x*w.x;
                acc.y += v.y*w.y;
            }
        float2 center = win[2][2];
        float2 r;
        r.x = center.x + gelu_exact(acc.x + bb.x);
        r.y = center.y + gelu_exact(acc.y + bb.y);
        size_t row = (size_t)(b*65536 + (y0+pq)*256 + (x0+px));
        *(float2*)(out + row*HID + c0) = r;
        if (px < 7) {
#pragma unroll
            for (int dx = 0; dx < 4; dx++)
#pragma unroll
                for (int dy = 0; dy < 5; dy++)
                    win[dx][dy] = win[dx+1][dy];
#pragma unroll
            for (int dy = 0; dy < 5; dy++)
                win[4][dy] = s[(pq+dy)*12 + (px+5)][c2];
        }
    }
}

// ---------------- launch ----------------
extern "C" void kernel_launch(void* const* d_in, const int* in_sizes, int n_in,
                              void* d_out, int out_size) {
    const float* x          = (const float*)d_in[0];
    const float* g1         = (const float*)d_in[1];
    const float* be1        = (const float*)d_in[2];
    const float* wq         = (const float*)d_in[3];
    const float* bq         = (const float*)d_in[4];
    const float* wkv        = (const float*)d_in[5];
    const float* bkv        = (const float*)d_in[6];
    const float* bias_table = (const float*)d_in[7];
    const float* wproj      = (const float*)d_in[8];
    const float* bproj      = (const float*)d_in[9];
    const float* g2         = (const float*)d_in[10];
    const float* be2        = (const float*)d_in[11];
    const float* w1f        = (const float*)d_in[12];
    const float* b1f        = (const float*)d_in[13];
    const float* dwk        = (const float*)d_in[14];
    const float* dwb        = (const float*)d_in[15];
    const float* w2f        = (const float*)d_in[16];
    const float* b2f        = (const float*)d_in[17];
    float* out = (float*)d_out;

    float *bufA, *bufB, *bufC, *bufD, *bufE;
    float *wq32, *wkv32, *wproj32, *w1f32, *w2f32;
    cudaGetSymbolAddress((void**)&bufA, g_bufA);
    cudaGetSymbolAddress((void**)&bufB, g_bufB);
    cudaGetSymbolAddress((void**)&bufC, g_bufC);
    cudaGetSymbolAddress((void**)&bufD, g_bufD);
    cudaGetSymbolAddress((void**)&bufE, g_bufE);
    cudaGetSymbolAddress((void**)&wq32,    g_wq32);
    cudaGetSymbolAddress((void**)&wkv32,   g_wkv32);
    cudaGetSymbolAddress((void**)&wproj32, g_wproj32);
    cudaGetSymbolAddress((void**)&w1f32,   g_w1f32);
    cudaGetSymbolAddress((void**)&w2f32,   g_w2f32);

    const int smB = 2*STG*STGB;   // 81920 bytes
    cudaFuncSetAttribute(mma_gemm<1>, cudaFuncAttributeMaxDynamicSharedMemorySize, smB);
    cudaFuncSetAttribute(mma_gemm<2>, cudaFuncAttributeMaxDynamicSharedMemorySize, smB);
    cudaFuncSetAttribute(mma_gemm<3>, cudaFuncAttributeMaxDynamicSharedMemorySize, smB);

    // 0. weight transposes (fp32 [N][K])
    wtrans32_kernel<<<dim3(6, 6),  256>>>(wq,    wq32,    192, 192);
    wtrans32_kernel<<<dim3(3, 6),  256>>>(wkv,   wkv32,   192, 96);
    wtrans32_kernel<<<dim3(6, 6),  256>>>(wproj, wproj32, 192, 192);
    wtrans32_kernel<<<dim3(24, 6), 256>>>(w1f,   w1f32,   192, 768);
    wtrans32_kernel<<<dim3(6, 24), 256>>>(w2f,   w2f32,   768, 192);

    // 1. LN1
    ln_kernel<<<TOK/8, 256>>>(x, g1, be1, bufA);
    // 2. q = xn @ wq + bq
    mma_gemm<1><<<dim3(2, TOK/BM), 256, smB>>>(bufA, wq32, bq, nullptr, bufD, TOK, 192, 192);
    // 3. kv = xn @ wkv + bkv
    mma_gemm<1><<<dim3(1, TOK/BM), 256, smB>>>(bufA, wkv32, bkv, nullptr, bufE, TOK, 96, 192);
    // 4. attention
    attn_kernel<<<NWIN, 384>>>(bufD, bufE, bias_table, bufB);
    // 5. x2 = x + aw @ wproj + bproj
    mma_gemm<3><<<dim3(2, TOK/BM), 256, smB>>>(bufB, wproj32, bproj, x, bufC, TOK, 192, 192);
    // 6. LN2
    ln_kernel<<<TOK/8, 256>>>(bufC, g2, be2, bufA);
    // 7. h1 = gelu(xn2 @ w1f + b1f)
    mma_gemm<2><<<dim3(6, TOK/BM), 256, smB>>>(bufA, w1f32, b1f, nullptr, bufD, TOK, HID, 192);
    // 8. dwconv branch
    dwconv_kernel<<<dim3(32, 32, Bsz*12), 256>>>(bufD, dwk, dwb, bufE);
    // 9. out = x2 + h @ w2f + b2f
    mma_gemm<3><<<dim3(2, TOK/BM), 256, smB>>>(bufE, w2f32, b2f, bufC, out, TOK, 192, HID);
}

// round 7
// speedup vs baseline: 1.1803x; 1.1550x over previous
#include <cuda_runtime.h>
#include <math.h>
#include <stdint.h>

// ---------------- problem constants ----------------
#define Bsz     2
#define Hdim    256
#define Wdim    256
#define Cc      192
#define NHEADS  6
#define HID     768
#define TOK     (Bsz*Hdim*Wdim)      // 131072 tokens
#define NWIN    2048

// ---------------- scratch ----------------
__device__ float g_bufA[(size_t)TOK*Cc];    // xn / xn2
__device__ float g_qkv [(size_t)TOK*288];   // fused q|kv output
__device__ float g_bufB[(size_t)TOK*Cc];    // attention output (pre-proj)
__device__ float g_bufC[(size_t)TOK*Cc];    // x after attention residual
__device__ float g_bufD[(size_t)TOK*HID];   // h1
__device__ float g_bufE[(size_t)TOK*HID];   // h
__device__ float g_wqkv[192*288];           // [K][288] concat weights
__device__ float g_bqkv[288];

__device__ __forceinline__ float gelu_exact(float x) {
    return 0.5f * x * (1.0f + erff(x * 0.70710678118654752f));
}

__device__ __forceinline__ void cp_async16(uint32_t dst, const void* src) {
    asm volatile("cp.async.cg.shared.global [%0], [%1], 16;" :: "r"(dst), "l"(src));
}
__device__ __forceinline__ void cp_commit() {
    asm volatile("cp.async.commit_group;");
}
template<int N_>
__device__ __forceinline__ void cp_wait() {
    asm volatile("cp.async.wait_group %0;" :: "n"(N_));
}

// ---------------- concat weight prep ----------------
__global__ __launch_bounds__(256)
void wcat_kernel(const float* __restrict__ wq, const float* __restrict__ wkv,
                 const float* __restrict__ bq, const float* __restrict__ bkv,
                 float* __restrict__ W, float* __restrict__ bv) {
    int i = blockIdx.x * 256 + threadIdx.x;
    if (i < 192*288) {
        int k = i / 288, c = i % 288;
        W[i] = (c < 192) ? wq[k*192 + c] : wkv[k*96 + (c - 192)];
    }
    if (i < 288) bv[i] = (i < 192) ? bq[i] : bkv[i - 192];
}

// ---------------- LayerNorm ----------------
__global__ __launch_bounds__(256)
void ln_kernel(const float* __restrict__ x, const float* __restrict__ g,
               const float* __restrict__ b, float* __restrict__ out) {
    int warp = (blockIdx.x * blockDim.x + threadIdx.x) >> 5;
    int lane = threadIdx.x & 31;
    if (warp >= TOK) return;
    const float* xr = x + (size_t)warp * Cc;
    float v[6];
    float s = 0.f, s2 = 0.f;
#pragma unroll
    for (int j = 0; j < 6; j++) {
        v[j] = xr[lane + 32*j];
        s += v[j]; s2 += v[j]*v[j];
    }
#pragma unroll
    for (int o = 16; o; o >>= 1) {
        s  += __shfl_xor_sync(0xffffffffu, s,  o);
        s2 += __shfl_xor_sync(0xffffffffu, s2, o);
    }
    float mu  = s  * (1.f/Cc);
    float var = s2 * (1.f/Cc) - mu*mu;
    float r   = rsqrtf(var + 1e-5f);
    float* orow = out + (size_t)warp * Cc;
#pragma unroll
    for (int j = 0; j < 6; j++) {
        int c = lane + 32*j;
        orow[c] = (v[j]-mu)*r*g[c] + b[c];
    }
}

// ---------------- hybrid HMMA(tf32) + FFMA(fp32) GEMM ----------------
// C[M,N] = A[M,K] @ W[K,N] (+bias)(+gelu)(+res)
// Tile: 128 rows x (NH HMMA cols + 32 SIMT cols). 256 threads, 8 warps (2x4).
// HMMA warp tile 64 x (NH/4); SIMT: thread (tr=tid>>3, tc=tid&7) -> 4x4 micro at cols NH+tc*4.
// 2-stage cp.async (R3-proven). EPI: 1=bias, 2=bias+gelu, 3=bias+residual
template<int NH, int EPI>
__global__ __launch_bounds__(256, 2)
void hyb_gemm(const float* __restrict__ A, const float* __restrict__ Wt,
              const float* __restrict__ bias, const float* __restrict__ res,
              float* __restrict__ C, int M, int N, int K) {
    constexpr int NT  = NH + 32;       // total cols per tile
    constexpr int NTN = NH / 32;       // HMMA n-frags per warp (4 or 5)
    constexpr int SB  = NT + 8;        // B smem stride (floats)
    __shared__ float As[2][128][20];   // [m][k]
    __shared__ float Bs[2][16][SB];    // [k][n]

    const int tid  = threadIdx.x;
    const int lane = tid & 31;
    const int warp = tid >> 5;
    const int wm = (warp >> 2) * 64;
    const int wn = (warp & 3) * (NH/4);
    const int m0 = blockIdx.y * 128;
    const int n0 = blockIdx.x * NT;
    const int gr = lane >> 2;
    const int gc = lane & 3;
    const int tr = tid >> 3;           // 0..31 SIMT row group
    const int tc = tid & 7;            // 0..7 SIMT col group

    const uint32_t abase = (uint32_t)__cvta_generic_to_shared(&As[0][0][0]);
    const uint32_t bbase = (uint32_t)__cvta_generic_to_shared(&Bs[0][0][0]);

    float acc[4][NTN][4];
#pragma unroll
    for (int i = 0; i < 4; i++)
#pragma unroll
        for (int j = 0; j < NTN; j++)
#pragma unroll
            for (int t = 0; t < 4; t++) acc[i][j][t] = 0.f;
    float4 sacc[4];
#pragma unroll
    for (int i = 0; i < 4; i++) sacc[i] = make_float4(0.f,0.f,0.f,0.f);

    const int niter = K / 16;

    auto load_stage = [&](int s, int it) {
        const int k0 = it * 16;
        // A: 128 rows x 16 k -> As[s][m][k], 512 chunks, 2/thread
#pragma unroll
        for (int h = 0; h < 2; h++) {
            int f = tid + h*256;
            int row = f >> 2, c4 = (f & 3) * 4;
            cp_async16(abase + (uint32_t)((((s*128 + row)*20) + c4) * 4),
                       A + (size_t)(m0 + row)*K + k0 + c4);
        }
        // B: 16 k x NT cols -> Bs[s][k][n]
        for (int f = tid; f < 16*(NT/4); f += 256) {
            int k = f / (NT/4), c4 = (f % (NT/4)) * 4;
            int col = n0 + c4;
            cp_async16(bbase + (uint32_t)((((s*16 + k)*SB) + c4) * 4),
                       Wt + (size_t)(k0 + k)*N + (col < N ? col : 0));
        }
    };

    load_stage(0, 0);
    cp_commit();

    for (int it = 0; it < niter; it++) {
        if (it + 1 < niter) load_stage((it + 1) & 1, it + 1);
        cp_commit();
        cp_wait<1>();
        __syncthreads();

        const int s = it & 1;
#pragma unroll
        for (int ks = 0; ks < 2; ks++) {
            const int kb = ks * 8;
            // ---- HMMA fragments ----
            unsigned af[4][4];
#pragma unroll
            for (int mt = 0; mt < 4; mt++) {
                int mr = wm + mt*16 + gr;
                af[mt][0] = __float_as_uint(As[s][mr    ][kb + gc    ]);
                af[mt][1] = __float_as_uint(As[s][mr + 8][kb + gc    ]);
                af[mt][2] = __float_as_uint(As[s][mr    ][kb + gc + 4]);
                af[mt][3] = __float_as_uint(As[s][mr + 8][kb + gc + 4]);
            }
            unsigned bf[NTN][2];
#pragma unroll
            for (int nt = 0; nt < NTN; nt++) {
                int nc = wn + nt*8 + gr;
                bf[nt][0] = __float_as_uint(Bs[s][kb + gc    ][nc]);
                bf[nt][1] = __float_as_uint(Bs[s][kb + gc + 4][nc]);
            }
#pragma unroll
            for (int mt = 0; mt < 4; mt++)
#pragma unroll
                for (int nt = 0; nt < NTN; nt++) {
                    asm volatile(
                        "mma.sync.aligned.m16n8k8.row.col.f32.tf32.tf32.f32 "
                        "{%0,%1,%2,%3}, {%4,%5,%6,%7}, {%8,%9}, {%0,%1,%2,%3};"
                        : "+f"(acc[mt][nt][0]), "+f"(acc[mt][nt][1]),
                          "+f"(acc[mt][nt][2]), "+f"(acc[mt][nt][3])
                        : "r"(af[mt][0]), "r"(af[mt][1]), "r"(af[mt][2]), "r"(af[mt][3]),
                          "r"(bf[nt][0]), "r"(bf[nt][1]));
                }
            // ---- SIMT FFMA for cols NH..NH+31, k = kb..kb+7 ----
#pragma unroll
            for (int k4g = 0; k4g < 2; k4g++) {
                const int kk = kb + k4g*4;
                float4 b0 = *(const float4*)&Bs[s][kk+0][NH + tc*4];
                float4 b1 = *(const float4*)&Bs[s][kk+1][NH + tc*4];
                float4 b2 = *(const float4*)&Bs[s][kk+2][NH + tc*4];
                float4 b3 = *(const float4*)&Bs[s][kk+3][NH + tc*4];
#pragma unroll
                for (int i = 0; i < 4; i++) {
                    float4 a = *(const float4*)&As[s][tr*4 + i][kk];
                    sacc[i].x += a.x*b0.x + a.y*b1.x + a.z*b2.x + a.w*b3.x;
                    sacc[i].y += a.x*b0.y + a.y*b1.y + a.z*b2.y + a.w*b3.y;
                    sacc[i].z += a.x*b0.z + a.y*b1.z + a.z*b2.z + a.w*b3.z;
                    sacc[i].w += a.x*b0.w + a.y*b1.w + a.z*b2.w + a.w*b3.w;
                }
            }
        }
        __syncthreads();
    }

    // ---- HMMA epilogue ----
#pragma unroll
    for (int mt = 0; mt < 4; mt++) {
#pragma unroll
        for (int nt = 0; nt < NTN; nt++) {
            int col = n0 + wn + nt*8 + gc*2;
            if (col < N) {
#pragma unroll
                for (int hh = 0; hh < 2; hh++) {
                    int row = m0 + wm + mt*16 + gr + hh*8;
                    float v0 = acc[mt][nt][hh*2+0];
                    float v1 = acc[mt][nt][hh*2+1];
                    v0 += bias[col]; v1 += bias[col+1];
                    if (EPI == 2) { v0 = gelu_exact(v0); v1 = gelu_exact(v1); }
                    if (EPI == 3) {
                        const float* rr = res + (size_t)row*N + col;
                        v0 += rr[0]; v1 += rr[1];
                    }
                    *(float2*)(C + (size_t)row*N + col) = make_float2(v0, v1);
                }
            }
        }
    }
    // ---- SIMT epilogue ----
    {
        int col = n0 + NH + tc*4;
        if (col < N) {
#pragma unroll
            for (int i = 0; i < 4; i++) {
                int row = m0 + tr*4 + i;
                float4 v = sacc[i];
                v.x += bias[col]; v.y += bias[col+1]; v.z += bias[col+2]; v.w += bias[col+3];
                if (EPI == 2) { v.x = gelu_exact(v.x); v.y = gelu_exact(v.y);
                                v.z = gelu_exact(v.z); v.w = gelu_exact(v.w); }
                if (EPI == 3) {
                    float4 rr = *(const float4*)(res + (size_t)row*N + col);
                    v.x += rr.x; v.y += rr.y; v.z += rr.z; v.w += rr.w;
                }
                *(float4*)(C + (size_t)row*N + col) = v;
            }
        }
    }
}

// ---------------- fused windowed attention (reads fused qkv, stride 288) ----------------
__global__ __launch_bounds__(384)
void attn_kernel(const float* __restrict__ qkv, const float* __restrict__ bias_table,
                 float* __restrict__ aw) {
    __shared__ float sk[NHEADS*16*32];
    __shared__ float sv[NHEADS*16*32];
    const int wid = blockIdx.x;
    const int b  = wid >> 10;
    const int wy = (wid >> 5) & 31;
    const int wx = wid & 31;
    const int base = b*65536 + wy*8*256 + wx*8;
    const int tid = threadIdx.x;

    for (int ii = tid; ii < 2*16*192; ii += 384) {
        int sel = ii / (16*192);
        int rem = ii - sel*(16*192);
        int tok = rem / 192;
        int hd  = rem - tok*192;
        int i   = hd / 96;
        int j   = (hd / 48) & 1;
        int c48 = hd % 48;
        int p1 = tok >> 2, p2 = tok & 3;
        int grow = base + (p1*2 + i)*256 + (p2*2 + j);
        float val = qkv[(size_t)grow*288 + 192 + sel*48 + c48];
        float* dst = sel ? sv : sk;
        dst[(hd >> 5)*512 + tok*32 + (hd & 31)] = val;
    }
    __syncthreads();

    const int h  = tid / 64;
    const int qt = tid % 64;
    const int qr = qt >> 3, qc = qt & 7;
    const int qrow = base + qr*256 + qc;

    float q[32];
    const float* qp = qkv + (size_t)qrow*288 + h*32;
#pragma unroll
    for (int d4 = 0; d4 < 8; d4++) {
        float4 t = *(const float4*)(qp + d4*4);
        q[d4*4+0]=t.x; q[d4*4+1]=t.y; q[d4*4+2]=t.z; q[d4*4+3]=t.w;
    }

    const float SCALE = 0.17677669529663687f;
    const int qr2 = qr >> 1, qc2 = qc >> 1;
    float sc[16];
    float m = -1e30f;
#pragma unroll
    for (int kv = 0; kv < 16; kv++) {
        const float* kp = sk + h*512 + kv*32;
        float dot = 0.f;
#pragma unroll
        for (int d = 0; d < 32; d++) dot += q[d]*kp[d];
        int kr = kv >> 2, kc = kv & 3;
        int rel = (qr2 - kr + 3)*7 + (qc2 - kc + 3);
        float s = dot*SCALE + bias_table[rel*NHEADS + h];
        sc[kv] = s;
        m = fmaxf(m, s);
    }
    float sum = 0.f;
#pragma unroll
    for (int kv = 0; kv < 16; kv++) { sc[kv] = expf(sc[kv]-m); sum += sc[kv]; }
    float inv = 1.f/sum;
    float o[32];
#pragma unroll
    for (int d = 0; d < 32; d++) o[d] = 0.f;
#pragma unroll
    for (int kv = 0; kv < 16; kv++) {
        float p = sc[kv]*inv;
        const float* vp = sv + h*512 + kv*32;
#pragma unroll
        for (int d = 0; d < 32; d++) o[d] += p*vp[d];
    }
    float* op = aw + (size_t)qrow*Cc + h*32;
#pragma unroll
    for (int d4 = 0; d4 < 8; d4++) {
        *(float4*)(op + d4*4) = make_float4(o[d4*4+0],o[d4*4+1],o[d4*4+2],o[d4*4+3]);
    }
}

// ---------------- depthwise 5x5 conv branch ----------------
__global__ __launch_bounds__(256)
void dwconv_kernel(const float* __restrict__ h1, const float* __restrict__ dwk,
                   const float* __restrict__ dwb, float* __restrict__ out) {
    __shared__ float2 s[144][32];
    const int cb = blockIdx.z % 12;
    const int b  = blockIdx.z / 12;
    const int y0 = blockIdx.y * 8, x0 = blockIdx.x * 8;
    const int tid = threadIdx.x;

    for (int ii = tid; ii < 144*32; ii += 256) {
        int pix = ii >> 5, c2 = ii & 31;
        int py = pix / 12, px = pix % 12;
        int gy = y0 + py - 2, gx = x0 + px - 2;
        float2 v = make_float2(0.f, 0.f);
        if (gy >= 0 && gy < Hdim && gx >= 0 && gx < Wdim) {
            size_t row = (size_t)(b*65536 + gy*256 + gx);
            v = *(const float2*)(h1 + row*HID + cb*64 + c2*2);
        }
        s[pix][c2] = v;
    }
    __syncthreads();

    const int c2 = tid & 31;
    const int pq = tid >> 5;
    const int c0 = cb*64 + c2*2;

    float2 wk[25];
#pragma unroll
    for (int t = 0; t < 25; t++) {
        wk[t].x = dwk[(size_t)c0*25 + t];
        wk[t].y = dwk[(size_t)(c0+1)*25 + t];
    }
    float2 bb = make_float2(dwb[c0], dwb[c0+1]);

    float2 win[5][5];
#pragma unroll
    for (int dx = 0; dx < 5; dx++)
#pragma unroll
        for (int dy = 0; dy < 5; dy++)
            win[dx][dy] = s[(pq+dy)*12 + dx][c2];

#pragma unroll
    for (int px = 0; px < 8; px++) {
        float2 acc = make_float2(0.f, 0.f);
#pragma unroll
        for (int dy = 0; dy < 5; dy++)
#pragma unroll
            for (int dx = 0; dx < 5; dx++) {
                float2 v = win[dx][dy];
                float2 w = wk[dy*5+dx];
                acc.x += v.x*w.x;
                acc.y += v.y*w.y;
            }
        float2 center = win[2][2];
        float2 r;
        r.x = center.x + gelu_exact(acc.x + bb.x);
        r.y = center.y + gelu_exact(acc.y + bb.y);
        size_t row = (size_t)(b*65536 + (y0+pq)*256 + (x0+px));
        *(float2*)(out + row*HID + c0) = r;
        if (px < 7) {
#pragma unroll
            for (int dx = 0; dx < 4; dx++)
#pragma unroll
                for (int dy = 0; dy < 5; dy++)
                    win[dx][dy] = win[dx+1][dy];
#pragma unroll
            for (int dy = 0; dy < 5; dy++)
                win[4][dy] = s[(pq+dy)*12 + (px+5)][c2];
        }
    }
}

// ---------------- launch ----------------
extern "C" void kernel_launch(void* const* d_in, const int* in_sizes, int n_in,
                              void* d_out, int out_size) {
    const float* x          = (const float*)d_in[0];
    const float* g1         = (const float*)d_in[1];
    const float* be1        = (const float*)d_in[2];
    const float* wq         = (const float*)d_in[3];
    const float* bq         = (const float*)d_in[4];
    const float* wkv        = (const float*)d_in[5];
    const float* bkv        = (const float*)d_in[6];
    const float* bias_table = (const float*)d_in[7];
    const float* wproj      = (const float*)d_in[8];
    const float* bproj      = (const float*)d_in[9];
    const float* g2         = (const float*)d_in[10];
    const float* be2        = (const float*)d_in[11];
    const float* w1f        = (const float*)d_in[12];
    const float* b1f        = (const float*)d_in[13];
    const float* dwk        = (const float*)d_in[14];
    const float* dwb        = (const float*)d_in[15];
    const float* w2f        = (const float*)d_in[16];
    const float* b2f        = (const float*)d_in[17];
    float* out = (float*)d_out;

    float *bufA, *qkv, *bufB, *bufC, *bufD, *bufE, *wqkv, *bqkv;
    cudaGetSymbolAddress((void**)&bufA, g_bufA);
    cudaGetSymbolAddress((void**)&qkv,  g_qkv);
    cudaGetSymbolAddress((void**)&bufB, g_bufB);
    cudaGetSymbolAddress((void**)&bufC, g_bufC);
    cudaGetSymbolAddress((void**)&bufD, g_bufD);
    cudaGetSymbolAddress((void**)&bufE, g_bufE);
    cudaGetSymbolAddress((void**)&wqkv, g_wqkv);
    cudaGetSymbolAddress((void**)&bqkv, g_bqkv);

    // 0. concat q|kv weights
    wcat_kernel<<<(192*288 + 255)/256, 256>>>(wq, wkv, bq, bkv, wqkv, bqkv);
    // 1. LN1
    ln_kernel<<<TOK/8, 256>>>(x, g1, be1, bufA);
    // 2. qkv = xn @ [wq|wkv] + [bq|bkv]   (N=288, 2 x T160 tiles: 160+128, zero HMMA waste)
    hyb_gemm<128,1><<<dim3(2, TOK/128), 256>>>(bufA, wqkv, bqkv, nullptr, qkv, TOK, 288, 192);
    // 3. attention
    attn_kernel<<<NWIN, 384>>>(qkv, bias_table, bufB);
    // 4. x2 = x + aw @ wproj + bproj   (N=192, one T192 tile)
    hyb_gemm<160,3><<<dim3(1, TOK/128), 256>>>(bufB, wproj, bproj, x, bufC, TOK, 192, 192);
    // 5. LN2
    ln_kernel<<<TOK/8, 256>>>(bufC, g2, be2, bufA);
    // 6. h1 = gelu(xn2 @ w1f + b1f)   (N=768 = 4 x T192, exact)
    hyb_gemm<160,2><<<dim3(4, TOK/128), 256>>>(bufA, w1f, b1f, nullptr, bufD, TOK, HID, 192);
    // 7. h = h1 + gelu(dwconv(h1)+dwb)
    dwconv_kernel<<<dim3(32, 32, Bsz*12), 256>>>(bufD, dwk, dwb, bufE);
    // 8. out = x2 + h @ w2f + b2f   (N=192, one T192 tile, K=768)
    hyb_gemm<160,3><<<dim3(1, TOK/128), 256>>>(bufE, w2f, b2f, bufC, out, TOK, 192, HID);
}

// round 8
// speedup vs baseline: 1.4459x; 1.2251x over previous
#include <cuda_runtime.h>
#include <math.h>
#include <stdint.h>

// ---------------- problem constants ----------------
#define Bsz     2
#define Hdim    256
#define Wdim    256
#define Cc      192
#define NHEADS  6
#define HID     768
#define TOK     (Bsz*Hdim*Wdim)      // 131072 tokens
#define NWIN    2048

// ---------------- scratch ----------------
__device__ float g_bufA[(size_t)TOK*Cc];    // xn / xn2
__device__ float g_bufB[(size_t)TOK*Cc];    // attention output (pre-proj)
__device__ float g_bufC[(size_t)TOK*Cc];    // x after attention residual
__device__ float g_bufD[(size_t)TOK*HID];   // q, later h1
__device__ float g_bufE[(size_t)TOK*HID];   // kv, later h

__device__ __forceinline__ float gelu_exact(float x) {
    return 0.5f * x * (1.0f + erff(x * 0.70710678118654752f));
}

__device__ __forceinline__ void cp_async16(uint32_t dst, const void* src) {
    asm volatile("cp.async.cg.shared.global [%0], [%1], 16;" :: "r"(dst), "l"(src));
}
__device__ __forceinline__ void cp_commit() {
    asm volatile("cp.async.commit_group;");
}
template<int N_>
__device__ __forceinline__ void cp_wait() {
    asm volatile("cp.async.wait_group %0;" :: "n"(N_));
}

// ---------------- LayerNorm ----------------
__global__ __launch_bounds__(256)
void ln_kernel(const float* __restrict__ x, const float* __restrict__ g,
               const float* __restrict__ b, float* __restrict__ out) {
    int warp = (blockIdx.x * blockDim.x + threadIdx.x) >> 5;
    int lane = threadIdx.x & 31;
    if (warp >= TOK) return;
    const float* xr = x + (size_t)warp * Cc;
    float v[6];
    float s = 0.f, s2 = 0.f;
#pragma unroll
    for (int j = 0; j < 6; j++) {
        v[j] = xr[lane + 32*j];
        s += v[j]; s2 += v[j]*v[j];
    }
#pragma unroll
    for (int o = 16; o; o >>= 1) {
        s  += __shfl_xor_sync(0xffffffffu, s,  o);
        s2 += __shfl_xor_sync(0xffffffffu, s2, o);
    }
    float mu  = s  * (1.f/Cc);
    float var = s2 * (1.f/Cc) - mu*mu;
    float r   = rsqrtf(var + 1e-5f);
    float* orow = out + (size_t)warp * Cc;
#pragma unroll
    for (int j = 0; j < 6; j++) {
        int c = lane + 32*j;
        orow[c] = (v[j]-mu)*r*g[c] + b[c];
    }
}

// ---------------- tf32 tensor-core GEMM, exact-width tiles ----------------
// C[M,N] = A[M,K] @ W[K,N] (+bias)(+gelu)(+res).  W is [K][N] (original layout).
// Tile 128 x (NTN*32) x 16; 256 threads, 8 warps (2 m x 4 n); warp tile 64 x (NTN*8).
// Identical inner-loop structure to the proven R3 kernel; only the N width is templated.
// EPI: 1=bias, 2=bias+gelu, 3=bias+residual
#define BM 128
#define BK 16

template<int NTN, int EPI>
__global__ __launch_bounds__(256)
void mma_gemm(const float* __restrict__ A, const float* __restrict__ Wt,
              const float* __restrict__ bias, const float* __restrict__ res,
              float* __restrict__ C, int M, int N, int K) {
    constexpr int BN = NTN * 32;
    constexpr int SB = BN + 8;
    __shared__ float As[2][BM][20];    // [m][k], stride 20 (conflict-free)
    __shared__ float Bs[2][BK][SB];    // [k][n]

    const int tid  = threadIdx.x;
    const int lane = tid & 31;
    const int warp = tid >> 5;
    const int wm = (warp >> 2) * 64;
    const int wn = (warp & 3) * (NTN*8);
    const int m0 = blockIdx.y * BM;
    const int n0 = blockIdx.x * BN;
    const int gr = lane >> 2;
    const int gc = lane & 3;

    const uint32_t abase = (uint32_t)__cvta_generic_to_shared(&As[0][0][0]);
    const uint32_t bbase = (uint32_t)__cvta_generic_to_shared(&Bs[0][0][0]);

    float acc[4][NTN][4];
#pragma unroll
    for (int i = 0; i < 4; i++)
#pragma unroll
        for (int j = 0; j < NTN; j++)
#pragma unroll
            for (int t = 0; t < 4; t++) acc[i][j][t] = 0.f;

    const int niter = K / BK;

    auto load_stage = [&](int s, int it) {
        const int k0 = it * BK;
        // A: 128 x 16 = 512 float4 chunks, 2 per thread
#pragma unroll
        for (int h = 0; h < 2; h++) {
            int f = tid + h*256;
            int row = f >> 2, c4 = (f & 3) * 4;
            cp_async16(abase + (uint32_t)((((s*BM + row)*20) + c4) * 4),
                       A + (size_t)(m0 + row)*K + k0 + c4);
        }
        // B: 16 x BN floats = 16*(BN/4) float4 chunks
        for (int f = tid; f < 16*(BN/4); f += 256) {
            int k = f / (BN/4), c4 = (f % (BN/4)) * 4;
            cp_async16(bbase + (uint32_t)((((s*BK + k)*SB) + c4) * 4),
                       Wt + (size_t)(k0 + k)*N + n0 + c4);
        }
    };

    load_stage(0, 0);
    cp_commit();

    for (int it = 0; it < niter; it++) {
        if (it + 1 < niter) load_stage((it + 1) & 1, it + 1);
        cp_commit();
        cp_wait<1>();
        __syncthreads();

        const int s = it & 1;
#pragma unroll
        for (int ks = 0; ks < 2; ks++) {
            const int kb = ks * 8;
            unsigned af[4][4];
#pragma unroll
            for (int mt = 0; mt < 4; mt++) {
                int mr = wm + mt*16 + gr;
                af[mt][0] = __float_as_uint(As[s][mr    ][kb + gc    ]);
                af[mt][1] = __float_as_uint(As[s][mr + 8][kb + gc    ]);
                af[mt][2] = __float_as_uint(As[s][mr    ][kb + gc + 4]);
                af[mt][3] = __float_as_uint(As[s][mr + 8][kb + gc + 4]);
            }
            unsigned bf[NTN][2];
#pragma unroll
            for (int nt = 0; nt < NTN; nt++) {
                int nc = wn + nt*8 + gr;
                bf[nt][0] = __float_as_uint(Bs[s][kb + gc    ][nc]);
                bf[nt][1] = __float_as_uint(Bs[s][kb + gc + 4][nc]);
            }
#pragma unroll
            for (int mt = 0; mt < 4; mt++)
#pragma unroll
                for (int nt = 0; nt < NTN; nt++) {
                    asm volatile(
                        "mma.sync.aligned.m16n8k8.row.col.f32.tf32.tf32.f32 "
                        "{%0,%1,%2,%3}, {%4,%5,%6,%7}, {%8,%9}, {%0,%1,%2,%3};"
                        : "+f"(acc[mt][nt][0]), "+f"(acc[mt][nt][1]),
                          "+f"(acc[mt][nt][2]), "+f"(acc[mt][nt][3])
                        : "r"(af[mt][0]), "r"(af[mt][1]), "r"(af[mt][2]), "r"(af[mt][3]),
                          "r"(bf[nt][0]), "r"(bf[nt][1]));
                }
        }
        __syncthreads();
    }

    // ---- epilogue ----
#pragma unroll
    for (int mt = 0; mt < 4; mt++) {
#pragma unroll
        for (int nt = 0; nt < NTN; nt++) {
            int col = n0 + wn + nt*8 + gc*2;
#pragma unroll
            for (int hh = 0; hh < 2; hh++) {
                int row = m0 + wm + mt*16 + gr + hh*8;
                float v0 = acc[mt][nt][hh*2+0];
                float v1 = acc[mt][nt][hh*2+1];
                v0 += bias[col]; v1 += bias[col+1];
                if (EPI == 2) { v0 = gelu_exact(v0); v1 = gelu_exact(v1); }
                if (EPI == 3) {
                    const float* rr = res + (size_t)row*N + col;
                    v0 += rr[0]; v1 += rr[1];
                }
                *(float2*)(C + (size_t)row*N + col) = make_float2(v0, v1);
            }
        }
    }
}

// ---------------- fused windowed attention ----------------
__global__ __launch_bounds__(384)
void attn_kernel(const float* __restrict__ qbuf, const float* __restrict__ kvbuf,
                 const float* __restrict__ bias_table, float* __restrict__ aw) {
    __shared__ float sk[NHEADS*16*32];
    __shared__ float sv[NHEADS*16*32];
    const int wid = blockIdx.x;
    const int b  = wid >> 10;
    const int wy = (wid >> 5) & 31;
    const int wx = wid & 31;
    const int base = b*65536 + wy*8*256 + wx*8;
    const int tid = threadIdx.x;

    for (int ii = tid; ii < 2*16*192; ii += 384) {
        int sel = ii / (16*192);
        int rem = ii - sel*(16*192);
        int tok = rem / 192;
        int hd  = rem - tok*192;
        int i   = hd / 96;
        int j   = (hd / 48) & 1;
        int c48 = hd % 48;
        int p1 = tok >> 2, p2 = tok & 3;
        int grow = base + (p1*2 + i)*256 + (p2*2 + j);
        float val = kvbuf[(size_t)grow*96 + sel*48 + c48];
        float* dst = sel ? sv : sk;
        dst[(hd >> 5)*512 + tok*32 + (hd & 31)] = val;
    }
    __syncthreads();

    const int h  = tid / 64;
    const int qt = tid % 64;
    const int qr = qt >> 3, qc = qt & 7;
    const int qrow = base + qr*256 + qc;

    float q[32];
    const float* qp = qbuf + (size_t)qrow*Cc + h*32;
#pragma unroll
    for (int d4 = 0; d4 < 8; d4++) {
        float4 t = *(const float4*)(qp + d4*4);
        q[d4*4+0]=t.x; q[d4*4+1]=t.y; q[d4*4+2]=t.z; q[d4*4+3]=t.w;
    }

    const float SCALE = 0.17677669529663687f;
    const int qr2 = qr >> 1, qc2 = qc >> 1;
    float sc[16];
    float m = -1e30f;
#pragma unroll
    for (int kv = 0; kv < 16; kv++) {
        const float* kp = sk + h*512 + kv*32;
        float dot = 0.f;
#pragma unroll
        for (int d = 0; d < 32; d++) dot += q[d]*kp[d];
        int kr = kv >> 2, kc = kv & 3;
        int rel = (qr2 - kr + 3)*7 + (qc2 - kc + 3);
        float s = dot*SCALE + bias_table[rel*NHEADS + h];
        sc[kv] = s;
        m = fmaxf(m, s);
    }
    float sum = 0.f;
#pragma unroll
    for (int kv = 0; kv < 16; kv++) { sc[kv] = expf(sc[kv]-m); sum += sc[kv]; }
    float inv = 1.f/sum;
    float o[32];
#pragma unroll
    for (int d = 0; d < 32; d++) o[d] = 0.f;
#pragma unroll
    for (int kv = 0; kv < 16; kv++) {
        float p = sc[kv]*inv;
        const float* vp = sv + h*512 + kv*32;
#pragma unroll
        for (int d = 0; d < 32; d++) o[d] += p*vp[d];
    }
    float* op = aw + (size_t)qrow*Cc + h*32;
#pragma unroll
    for (int d4 = 0; d4 < 8; d4++) {
        *(float4*)(op + d4*4) = make_float4(o[d4*4+0],o[d4*4+1],o[d4*4+2],o[d4*4+3]);
    }
}

// ---------------- depthwise 5x5 conv branch ----------------
__global__ __launch_bounds__(256)
void dwconv_kernel(const float* __restrict__ h1, const float* __restrict__ dwk,
                   const float* __restrict__ dwb, float* __restrict__ out) {
    __shared__ float2 s[144][32];
    const int cb = blockIdx.z % 12;
    const int b  = blockIdx.z / 12;
    const int y0 = blockIdx.y * 8, x0 = blockIdx.x * 8;
    const int tid = threadIdx.x;

    for (int ii = tid; ii < 144*32; ii += 256) {
        int pix = ii >> 5, c2 = ii & 31;
        int py = pix / 12, px = pix % 12;
        int gy = y0 + py - 2, gx = x0 + px - 2;
        float2 v = make_float2(0.f, 0.f);
        if (gy >= 0 && gy < Hdim && gx >= 0 && gx < Wdim) {
            size_t row = (size_t)(b*65536 + gy*256 + gx);
            v = *(const float2*)(h1 + row*HID + cb*64 + c2*2);
        }
        s[pix][c2] = v;
    }
    __syncthreads();

    const int c2 = tid & 31;
    const int pq = tid >> 5;
    const int c0 = cb*64 + c2*2;

    float2 wk[25];
#pragma unroll
    for (int t = 0; t < 25; t++) {
        wk[t].x = dwk[(size_t)c0*25 + t];
        wk[t].y = dwk[(size_t)(c0+1)*25 + t];
    }
    float2 bb = make_float2(dwb[c0], dwb[c0+1]);

    float2 win[5][5];
#pragma unroll
    for (int dx = 0; dx < 5; dx++)
#pragma unroll
        for (int dy = 0; dy < 5; dy++)
            win[dx][dy] = s[(pq+dy)*12 + dx][c2];

#pragma unroll
    for (int px = 0; px < 8; px++) {
        float2 acc = make_float2(0.f, 0.f);
#pragma unroll
        for (int dy = 0; dy < 5; dy++)
#pragma unroll
            for (int dx = 0; dx < 5; dx++) {
                float2 v = win[dx][dy];
                float2 w = wk[dy*5+dx];
                acc.x += v.x*w.x;
                acc.y += v.y*w.y;
            }
        float2 center = win[2][2];
        float2 r;
        r.x = center.x + gelu_exact(acc.x + bb.x);
        r.y = center.y + gelu_exact(acc.y + bb.y);
        size_t row = (size_t)(b*65536 + (y0+pq)*256 + (x0+px));
        *(float2*)(out + row*HID + c0) = r;
        if (px < 7) {
#pragma unroll
            for (int dx = 0; dx < 4; dx++)
#pragma unroll
                for (int dy = 0; dy < 5; dy++)
                    win[dx][dy] = win[dx+1][dy];
#pragma unroll
            for (int dy = 0; dy < 5; dy++)
                win[4][dy] = s[(pq+dy)*12 + (px+5)][c2];
        }
    }
}

// ---------------- launch ----------------
extern "C" void kernel_launch(void* const* d_in, const int* in_sizes, int n_in,
                              void* d_out, int out_size) {
    const float* x          = (const float*)d_in[0];
    const float* g1         = (const float*)d_in[1];
    const float* be1        = (const float*)d_in[2];
    const float* wq         = (const float*)d_in[3];
    const float* bq         = (const float*)d_in[4];
    const float* wkv        = (const float*)d_in[5];
    const float* bkv        = (const float*)d_in[6];
    const float* bias_table = (const float*)d_in[7];
    const float* wproj      = (const float*)d_in[8];
    const float* bproj      = (const float*)d_in[9];
    const float* g2         = (const float*)d_in[10];
    const float* be2        = (const float*)d_in[11];
    const float* w1f        = (const float*)d_in[12];
    const float* b1f        = (const float*)d_in[13];
    const float* dwk        = (const float*)d_in[14];
    const float* dwb        = (const float*)d_in[15];
    const float* w2f        = (const float*)d_in[16];
    const float* b2f        = (const float*)d_in[17];
    float* out = (float*)d_out;

    float *bufA, *bufB, *bufC, *bufD, *bufE;
    cudaGetSymbolAddress((void**)&bufA, g_bufA);
    cudaGetSymbolAddress((void**)&bufB, g_bufB);
    cudaGetSymbolAddress((void**)&bufC, g_bufC);
    cudaGetSymbolAddress((void**)&bufD, g_bufD);
    cudaGetSymbolAddress((void**)&bufE, g_bufE);

    // 1. LN1
    ln_kernel<<<TOK/8, 256>>>(x, g1, be1, bufA);
    // 2. q = xn @ wq + bq           (N=192 = 2 x 96, exact)
    mma_gemm<3,1><<<dim3(2, TOK/BM), 256>>>(bufA, wq, bq, nullptr, bufD, TOK, 192, 192);
    // 3. kv = xn @ wkv + bkv        (N=96 = 1 x 96, exact)
    mma_gemm<3,1><<<dim3(1, TOK/BM), 256>>>(bufA, wkv, bkv, nullptr, bufE, TOK, 96, 192);
    // 4. attention
    attn_kernel<<<NWIN, 384>>>(bufD, bufE, bias_table, bufB);
    // 5. x2 = x + aw @ wproj + bproj  (exact)
    mma_gemm<3,3><<<dim3(2, TOK/BM), 256>>>(bufB, wproj, bproj, x, bufC, TOK, 192, 192);
    // 6. LN2
    ln_kernel<<<TOK/8, 256>>>(bufC, g2, be2, bufA);
    // 7. h1 = gelu(xn2 @ w1f + b1f)   (N=768 = 8 x 96, exact)
    mma_gemm<3,2><<<dim3(8, TOK/BM), 256>>>(bufA, w1f, b1f, nullptr, bufD, TOK, HID, 192);
    // 8. h = h1 + gelu(dwconv(h1)+dwb)
    dwconv_kernel<<<dim3(32, 32, Bsz*12), 256>>>(bufD, dwk, dwb, bufE);
    // 9. out = x2 + h @ w2f + b2f     (N=192 = 2 x 96, K=768, exact)
    mma_gemm<3,3><<<dim3(2, TOK/BM), 256>>>(bufE, w2f, b2f, bufC, out, TOK, 192, HID);
}